// round 12
// baseline (speedup 1.0000x reference)
#include <cuda_runtime.h>
#include <cuda_fp16.h>
#include <cstdint>
#include <math.h>

#define MTOK   8192
#define DMODEL 1024
#define DFF    4096

// ---------------- scratch (device globals; no runtime allocation) ----------------
__device__ __half g_xh [(size_t)MTOK * DMODEL];   // x in fp16
__device__ __half g_w1t[(size_t)DFF  * DMODEL];   // W1^T fp16  [N=4096][K=1024]
__device__ __half g_w2t[(size_t)DMODEL * DFF];    // W2^T fp16  [N=1024][K=4096]
__device__ __half g_act[(size_t)MTOK * DFF];      // post-activation hidden, fp16
__device__ float  g_qp [DFF];                     // (cos(th)*wre + sin(th)*wim)*0.1

// ---------------- helpers ----------------
__device__ __forceinline__ uint32_t smem_u32(const void* p) {
    uint32_t a;
    asm("{ .reg .u64 t; cvta.to.shared.u64 t, %1; cvt.u32.u64 %0, t; }" : "=r"(a) : "l"(p));
    return a;
}
__device__ __forceinline__ void cp_async16(uint32_t saddr, const void* g) {
    asm volatile("cp.async.cg.shared.global [%0], [%1], 16;" :: "r"(saddr), "l"(g) : "memory");
}
__device__ __forceinline__ void ldsm_x4(uint32_t& r0, uint32_t& r1, uint32_t& r2, uint32_t& r3,
                                        uint32_t addr) {
    asm volatile("ldmatrix.sync.aligned.m8n8.x4.shared.b16 {%0,%1,%2,%3}, [%4];"
                 : "=r"(r0), "=r"(r1), "=r"(r2), "=r"(r3) : "r"(addr));
}
__device__ __forceinline__ void mma_f16(float* c, const uint32_t* a, const uint32_t* b) {
    asm volatile(
        "mma.sync.aligned.m16n8k16.row.col.f32.f16.f16.f32 "
        "{%0,%1,%2,%3}, {%4,%5,%6,%7}, {%8,%9}, {%0,%1,%2,%3};"
        : "+f"(c[0]), "+f"(c[1]), "+f"(c[2]), "+f"(c[3])
        : "r"(a[0]), "r"(a[1]), "r"(a[2]), "r"(a[3]), "r"(b[0]), "r"(b[1]));
}
__device__ __forceinline__ uint32_t sw128(uint32_t bo) { return bo ^ ((bo >> 3) & 0x70); }

// mbarrier primitives (baseline sm_100-legal)
#define MBAR_INIT(a, n)  asm volatile("mbarrier.init.shared.b64 [%0], %1;" :: "r"(a), "r"(n) : "memory")
#define MBAR_ARRIVE(a)   asm volatile("mbarrier.arrive.shared.b64 _, [%0];" :: "r"(a) : "memory")
#define CPASYNC_MBAR_ARRIVE(a) \
    asm volatile("cp.async.mbarrier.arrive.noinc.shared.b64 [%0];" :: "r"(a) : "memory")
#define MBAR_WAIT(a, ph) do {                                                             \
    uint32_t _m = (a), _p = (ph), _d;                                                     \
    asm volatile("{ .reg .pred p; mbarrier.try_wait.parity.acquire.cta.shared::cta.b64 p, [%1], %2; selp.b32 %0,1,0,p; }" \
        : "=r"(_d) : "r"(_m), "r"(_p) : "memory");                                        \
    if (!_d) {                                                                            \
        asm volatile("{ .reg .pred P1; WL_%=: mbarrier.try_wait.parity.acquire.cta.shared::cta.b64 P1, [%0], %1, 0x989680; @P1 bra.uni WD_%=; bra.uni WL_%=; WD_%=: }" \
            :: "r"(_m), "r"(_p) : "memory");                                              \
    } } while (0)

// ---------------- preprocessing kernels ----------------
#define PREP_XB (MTOK * DMODEL / 4 / 256)   // 8192 blocks for x
__global__ void prep_k(const float* __restrict__ x, __half* __restrict__ xh,
                       const float* __restrict__ th, const float* __restrict__ wre,
                       const float* __restrict__ wim, float* __restrict__ qp) {
    int b = blockIdx.x;
    if (b < PREP_XB) {
        int i = b * 256 + threadIdx.x;
        float4 v = ((const float4*)x)[i];
        __half2 h0 = __floats2half2_rn(v.x, v.y);
        __half2 h1 = __floats2half2_rn(v.z, v.w);
        uint2 o;
        o.x = *(uint32_t*)&h0;
        o.y = *(uint32_t*)&h1;
        ((uint2*)xh)[i] = o;
    } else {
        int i = (b - PREP_XB) * 256 + threadIdx.x;
        if (i < DFF) {
            float s, c; sincosf(th[i], &s, &c);
            qp[i] = (c * wre[i] + s * wim[i]) * 0.1f;
        }
    }
}
// Fused transpose of W1 (1024x4096) and W2 (4096x1024), fp32 -> fp16, one launch.
// Blocks [0,4096): W1 tiles; [4096,8192): W2 tiles. 32x32 tiles, 256 threads.
#define W1_TILES ((DFF / 32) * (DMODEL / 32))   // 4096
__global__ void transpose_both_k(const float* __restrict__ W1, __half* __restrict__ w1t,
                                 const float* __restrict__ W2, __half* __restrict__ w2t) {
    __shared__ float t[32][33];
    const float* in; __half* out; int R, C, tile;
    if (blockIdx.x < W1_TILES) { in = W1; out = w1t; R = DMODEL; C = DFF; tile = blockIdx.x; }
    else                        { in = W2; out = w2t; R = DFF; C = DMODEL; tile = blockIdx.x - W1_TILES; }
    const int tiles_x = C / 32;
    const int bx = (tile % tiles_x) * 32, by = (tile / tiles_x) * 32;
    const int tx = threadIdx.x & 31, ty = threadIdx.x >> 5;
#pragma unroll
    for (int i = 0; i < 32; i += 8)
        t[ty + i][tx] = in[(size_t)(by + ty + i) * C + bx + tx];
    __syncthreads();
#pragma unroll
    for (int i = 0; i < 32; i += 8)
        out[(size_t)(bx + ty + i) * R + by + tx] = __float2half_rn(t[tx][ty + i]);
}

// ---------------- fp16 mma.sync GEMM, mbarrier full/empty pipeline ----------------
// CTA 128x128xBK64, 4 warps (2m x 2n), warp tile 64x64. 3 stages; 2 CTAs/SM.
// Loads for chunk c+2 interleaved across the 4 k16 slices of chunk c (4 cp.async each);
// EMPTY released after the last LDSM of a chunk (stage smem dead before final MMAs).
#define BM 128
#define BN 128
#define BK 64
#define NSTAGE 3
#define A_BYTES (BM * BK * 2)                   // 16384
#define STAGE_BYTES ((BM + BN) * BK * 2)        // 32768
#define MBAR_OFF (NSTAGE * STAGE_BYTES)         // 98304
#define SMEM_BYTES (MBAR_OFF + 64)
#define NTHREADS 128

template <int KCHUNKS, bool FUSE_Q, typename OutT>
__global__ void __launch_bounds__(NTHREADS, 2)
h16_gemm(const __half* __restrict__ A, const __half* __restrict__ Bt,
         const float* __restrict__ bias,
         const float* __restrict__ theta, const float* __restrict__ wim,
         const float* __restrict__ qp,
         OutT* __restrict__ C, int Kdim, int Ndim)
{
    extern __shared__ char smem[];
    const uint32_t sb = smem_u32(smem);
    const int tid = threadIdx.x;
    const int wid = tid >> 5, lid = tid & 31;
    const int wm = wid & 1, wn = wid >> 1;            // warp grid 2(m) x 2(n)

    const uint32_t FULL  = sb + MBAR_OFF;              // full[s]  at +8*s
    const uint32_t EMPTY = sb + MBAR_OFF + 24;         // empty[s] at +8*s

    if (tid == 0) {
#pragma unroll
        for (int s = 0; s < NSTAGE; s++) {
            MBAR_INIT(FULL  + 8 * s, NTHREADS);
            MBAR_INIT(EMPTY + 8 * s, NTHREADS);
        }
    }
    __syncthreads();

    const int tile_n = blockIdx.x, tile_m = blockIdx.y;
    const __half* Ab = A  + (size_t)tile_m * BM * Kdim;
    const __half* Bb = Bt + (size_t)tile_n * BN * Kdim;

    float acc[4][8][4];                                // 128 regs
#pragma unroll
    for (int i = 0; i < 4; i++)
#pragma unroll
        for (int j = 0; j < 8; j++)
#pragma unroll
            for (int q = 0; q < 4; q++) acc[i][j][q] = 0.0f;

    // one quarter of a stage load: 2 A-chunks + 2 B-chunks (4 x cp.async16)
    auto load_quarter = [&](int c, int s, int q) {
        const uint32_t a_s = sb + s * STAGE_BYTES;
        const uint32_t b_s = a_s + A_BYTES;
        const __half* ag = Ab + c * BK;
        const __half* bg = Bb + c * BK;
#pragma unroll
        for (int i = 2 * q; i < 2 * q + 2; i++) {
            int f = tid + i * NTHREADS;
            int r = f >> 3, kc = f & 7;
            uint32_t bo = (uint32_t)(r * 128 + kc * 16);
            cp_async16(a_s + sw128(bo), ag + (size_t)r * Kdim + kc * 8);
        }
#pragma unroll
        for (int i = 2 * q; i < 2 * q + 2; i++) {
            int f = tid + i * NTHREADS;
            int r = f >> 3, kc = f & 7;
            uint32_t bo = (uint32_t)(r * 128 + kc * 16);
            cp_async16(b_s + sw128(bo), bg + (size_t)r * Kdim + kc * 8);
        }
    };

    // prologue: fill all 3 stages (chunks 0..2), arm each
#pragma unroll
    for (int c = 0; c < NSTAGE && c < KCHUNKS; c++) {
#pragma unroll
        for (int q = 0; q < 4; q++) load_quarter(c, c, q);
        CPASYNC_MBAR_ARRIVE(FULL + 8 * c);
    }

    // hoisted swizzled ldmatrix base offsets; ks*32 is XOR-composable (bits 5-6)
    const int a_row_base = wm * 64 + ((lid >> 3) & 1) * 8 + (lid & 7);
    const int a_byte     = ((lid >> 4) & 1) * 16;
    const int b_row_base = wn * 64 + ((lid >> 4) & 1) * 8 + (lid & 7);
    const int b_byte     = ((lid >> 3) & 1) * 16;
    const uint32_t a_off0 = sw128((uint32_t)(a_row_base * 128 + a_byte));
    const uint32_t b_off0 = sw128((uint32_t)(b_row_base * 128 + b_byte)) + A_BYTES;

    int cs = 0, cp = 0;        // consumer stage/parity
    int es = 0, ep = 0;        // producer-target stage/parity

    for (int c = 0; c < KCHUNKS; c++) {
        const bool need_load = (c >= 1) && (c + NSTAGE - 1 < KCHUNKS);
        const int  lc = c + NSTAGE - 1;
        if (need_load) MBAR_WAIT(EMPTY + 8 * es, ep);  // all threads done with chunk c-1

        MBAR_WAIT(FULL + 8 * cs, cp);                  // chunk c resident

        const uint32_t st = sb + cs * STAGE_BYTES;
        const uint32_t a0 = st + a_off0;
        const uint32_t b0 = st + b_off0;
#pragma unroll
        for (int ks = 0; ks < 4; ks++) {
            if (need_load) load_quarter(lc, es, ks);   // spread 16 issues over 4 slices

            const uint32_t kx = (uint32_t)(ks * 32);
            uint32_t af[4][4];
#pragma unroll
            for (int mt = 0; mt < 4; mt++)
                ldsm_x4(af[mt][0], af[mt][1], af[mt][2], af[mt][3],
                        (a0 + mt * 2048) ^ kx);
            uint32_t bf[8][2];
#pragma unroll
            for (int np = 0; np < 4; np++) {
                uint32_t r0, r1, r2, r3;
                ldsm_x4(r0, r1, r2, r3, (b0 + np * 2048) ^ kx);
                bf[np * 2 + 0][0] = r0; bf[np * 2 + 0][1] = r1;
                bf[np * 2 + 1][0] = r2; bf[np * 2 + 1][1] = r3;
            }
            if (ks == 3) MBAR_ARRIVE(EMPTY + 8 * cs);  // last smem read of chunk done

#pragma unroll
            for (int mt = 0; mt < 4; mt++)
#pragma unroll
                for (int nt = 0; nt < 8; nt++)
                    mma_f16(acc[mt][nt], af[mt], bf[nt]);
        }

        if (need_load) {
            CPASYNC_MBAR_ARRIVE(FULL + 8 * es);        // all 16 issues done -> arm
            if (++es == NSTAGE) { es = 0; ep ^= 1; }
        }
        if (++cs == NSTAGE) { cs = 0; cp ^= 1; }
    }

    // ---- epilogue ----
#pragma unroll
    for (int nt = 0; nt < 8; nt++) {
        const int n = tile_n * BN + wn * 64 + nt * 8 + (lid & 3) * 2;
        const float2 bb = *(const float2*)(bias + n);
        float2 th2 = {0.f, 0.f}, wi2 = {0.f, 0.f}, qp2 = {0.f, 0.f};
        if (FUSE_Q) {
            th2 = *(const float2*)(theta + n);
            wi2 = *(const float2*)(wim + n);
            qp2 = *(const float2*)(qp + n);
        }
#pragma unroll
        for (int mt = 0; mt < 4; mt++) {
#pragma unroll
            for (int h = 0; h < 2; h++) {
                const size_t row = (size_t)tile_m * BM + wm * 64 + mt * 16 + (lid >> 2) + h * 8;
                float v0 = acc[mt][nt][2 * h + 0] + bb.x;
                float v1 = acc[mt][nt][2 * h + 1] + bb.y;
                if (FUSE_Q) {
                    float im0 = wi2.x * __sinf(th2.x + v0 * 0.1f);
                    float im1 = wi2.y * __sinf(th2.y + v1 * 0.1f);
                    v0 = fmaf(qp2.x, im0, v0);
                    v1 = fmaf(qp2.y, im1, v1);
                    v0 = fmaxf(v0, 0.0f);
                    v1 = fmaxf(v1, 0.0f);
                }
                if (FUSE_Q) {
                    __half2 hv = __floats2half2_rn(v0, v1);
                    *(__half2*)((__half*)C + row * Ndim + n) = hv;
                } else {
                    *(float2*)((float*)C + row * Ndim + n) = make_float2(v0, v1);
                }
            }
        }
    }
}

// ---------------- host entry ----------------
extern "C" void kernel_launch(void* const* d_in, const int* in_sizes, int n_in,
                              void* d_out, int out_size)
{
    const float* x   = (const float*)d_in[0];
    const float* W1  = (const float*)d_in[1];
    const float* b1  = (const float*)d_in[2];
    const float* th  = (const float*)d_in[3];
    const float* wre = (const float*)d_in[4];
    const float* wim = (const float*)d_in[5];
    const float* W2  = (const float*)d_in[6];
    const float* b2  = (const float*)d_in[7];
    float* out = (float*)d_out;

    void *pxh, *pw1t, *pw2t, *pact, *pqp;
    cudaGetSymbolAddress(&pxh,  g_xh);
    cudaGetSymbolAddress(&pw1t, g_w1t);
    cudaGetSymbolAddress(&pw2t, g_w2t);
    cudaGetSymbolAddress(&pact, g_act);
    cudaGetSymbolAddress(&pqp,  g_qp);
    __half* xh  = (__half*)pxh;
    __half* w1t = (__half*)pw1t;
    __half* w2t = (__half*)pw2t;
    __half* act = (__half*)pact;
    float*  qp  = (float*)pqp;

    cudaFuncSetAttribute((const void*)h16_gemm<DMODEL / BK, true, __half>,
                         cudaFuncAttributeMaxDynamicSharedMemorySize, SMEM_BYTES);
    cudaFuncSetAttribute((const void*)h16_gemm<DFF / BK, false, float>,
                         cudaFuncAttributeMaxDynamicSharedMemorySize, SMEM_BYTES);

    // preprocessing: x->fp16 + qp; W1^T + W2^T fused into one launch
    prep_k<<<PREP_XB + DFF / 256, 256>>>(x, xh, th, wre, wim, qp);
    transpose_both_k<<<2 * W1_TILES, 256>>>(W1, w1t, W2, w2t);

    // GEMM1: act = fp16(relu(qt(x @ W1 + b1)))   [8192, 4096], grid (32, 64)
    h16_gemm<DMODEL / BK, true, __half><<<dim3(DFF / BN, MTOK / BM), NTHREADS, SMEM_BYTES>>>(
        xh, w1t, b1, th, wim, qp, act, DMODEL, DFF);

    // GEMM2: out = act @ W2 + b2                  [8192, 1024], grid (8, 64)
    h16_gemm<DFF / BK, false, float><<<dim3(DMODEL / BN, MTOK / BM), NTHREADS, SMEM_BYTES>>>(
        act, w2t, b2, nullptr, nullptr, nullptr, out, DFF, DMODEL);
}

// round 13
// speedup vs baseline: 1.0446x; 1.0446x over previous
#include <cuda_runtime.h>
#include <cuda_fp16.h>
#include <cstdint>
#include <math.h>

#define MTOK   8192
#define DMODEL 1024
#define DFF    4096

// ---------------- scratch (device globals; no runtime allocation) ----------------
__device__ __half g_xh [(size_t)MTOK * DMODEL];   // x in fp16
__device__ __half g_w1t[(size_t)DFF  * DMODEL];   // W1^T fp16  [N=4096][K=1024]
__device__ __half g_w2t[(size_t)DMODEL * DFF];    // W2^T fp16  [N=1024][K=4096]
__device__ __half g_act[(size_t)MTOK * DFF];      // post-activation hidden, fp16
__device__ float  g_qp [DFF];                     // (cos(th)*wre + sin(th)*wim)*0.1

// ---------------- helpers ----------------
__device__ __forceinline__ uint32_t smem_u32(const void* p) {
    uint32_t a;
    asm("{ .reg .u64 t; cvta.to.shared.u64 t, %1; cvt.u32.u64 %0, t; }" : "=r"(a) : "l"(p));
    return a;
}
__device__ __forceinline__ void cp_async16(uint32_t saddr, const void* g) {
    asm volatile("cp.async.cg.shared.global [%0], [%1], 16;" :: "r"(saddr), "l"(g) : "memory");
}
__device__ __forceinline__ void ldsm_x4(uint32_t& r0, uint32_t& r1, uint32_t& r2, uint32_t& r3,
                                        uint32_t addr) {
    asm volatile("ldmatrix.sync.aligned.m8n8.x4.shared.b16 {%0,%1,%2,%3}, [%4];"
                 : "=r"(r0), "=r"(r1), "=r"(r2), "=r"(r3) : "r"(addr));
}
__device__ __forceinline__ void mma_f16(float* c, const uint32_t* a, const uint32_t* b) {
    asm volatile(
        "mma.sync.aligned.m16n8k16.row.col.f32.f16.f16.f32 "
        "{%0,%1,%2,%3}, {%4,%5,%6,%7}, {%8,%9}, {%0,%1,%2,%3};"
        : "+f"(c[0]), "+f"(c[1]), "+f"(c[2]), "+f"(c[3])
        : "r"(a[0]), "r"(a[1]), "r"(a[2]), "r"(a[3]), "r"(b[0]), "r"(b[1]));
}
__device__ __forceinline__ uint32_t sw128(uint32_t bo) { return bo ^ ((bo >> 3) & 0x70); }

// mbarrier primitives (baseline sm_100-legal)
#define MBAR_INIT(a, n)  asm volatile("mbarrier.init.shared.b64 [%0], %1;" :: "r"(a), "r"(n) : "memory")
#define MBAR_ARRIVE(a)   asm volatile("mbarrier.arrive.shared.b64 _, [%0];" :: "r"(a) : "memory")
#define CPASYNC_MBAR_ARRIVE(a) \
    asm volatile("cp.async.mbarrier.arrive.noinc.shared.b64 [%0];" :: "r"(a) : "memory")
#define MBAR_WAIT(a, ph) do {                                                             \
    uint32_t _m = (a), _p = (ph), _d;                                                     \
    asm volatile("{ .reg .pred p; mbarrier.try_wait.parity.acquire.cta.shared::cta.b64 p, [%1], %2; selp.b32 %0,1,0,p; }" \
        : "=r"(_d) : "r"(_m), "r"(_p) : "memory");                                        \
    if (!_d) {                                                                            \
        asm volatile("{ .reg .pred P1; WL_%=: mbarrier.try_wait.parity.acquire.cta.shared::cta.b64 P1, [%0], %1, 0x989680; @P1 bra.uni WD_%=; bra.uni WL_%=; WD_%=: }" \
            :: "r"(_m), "r"(_p) : "memory");                                              \
    } } while (0)

// ---------------- single fused preprocessing kernel ----------------
// Blocks [0, XB):            x fp32 -> fp16 (4 elems/thread)
// Blocks [XB, XB+QB):        qp = (cos(th)*wre + sin(th)*wim)*0.1
// Blocks [XB+QB, +W1T):      W1 (1024x4096) -> w1t fp16 transpose, 32x32 tiles
// Blocks [XB+QB+W1T, +W2T):  W2 (4096x1024) -> w2t fp16 transpose
#define PREP_XB  (MTOK * DMODEL / 4 / 256)          // 8192
#define PREP_QB  (DFF / 256)                        // 16
#define W1_TILES ((DFF / 32) * (DMODEL / 32))       // 4096
#define W2_TILES W1_TILES                           // 4096
#define PREP_BLOCKS (PREP_XB + PREP_QB + W1_TILES + W2_TILES)

__global__ void prep_all_k(const float* __restrict__ x, __half* __restrict__ xh,
                           const float* __restrict__ th, const float* __restrict__ wre,
                           const float* __restrict__ wim, float* __restrict__ qp,
                           const float* __restrict__ W1, __half* __restrict__ w1t,
                           const float* __restrict__ W2, __half* __restrict__ w2t) {
    __shared__ float t[32][33];
    int b = blockIdx.x;
    if (b < PREP_XB) {
        int i = b * 256 + threadIdx.x;
        float4 v = ((const float4*)x)[i];
        __half2 h0 = __floats2half2_rn(v.x, v.y);
        __half2 h1 = __floats2half2_rn(v.z, v.w);
        uint2 o;
        o.x = *(uint32_t*)&h0;
        o.y = *(uint32_t*)&h1;
        ((uint2*)xh)[i] = o;
        return;
    }
    b -= PREP_XB;
    if (b < PREP_QB) {
        int i = b * 256 + threadIdx.x;
        float s, c; sincosf(th[i], &s, &c);
        qp[i] = (c * wre[i] + s * wim[i]) * 0.1f;
        return;
    }
    b -= PREP_QB;
    const float* in; __half* out; int R, C, tile;
    if (b < W1_TILES) { in = W1; out = w1t; R = DMODEL; C = DFF;    tile = b; }
    else              { in = W2; out = w2t; R = DFF;    C = DMODEL; tile = b - W1_TILES; }
    const int tiles_x = C / 32;
    const int bx = (tile % tiles_x) * 32, by = (tile / tiles_x) * 32;
    const int tx = threadIdx.x & 31, ty = threadIdx.x >> 5;
#pragma unroll
    for (int i = 0; i < 32; i += 8)
        t[ty + i][tx] = in[(size_t)(by + ty + i) * C + bx + tx];
    __syncthreads();
#pragma unroll
    for (int i = 0; i < 32; i += 8)
        out[(size_t)(bx + ty + i) * R + by + tx] = __float2half_rn(t[tx][ty + i]);
}

// ---------------- fp16 mma.sync GEMM, mbarrier full/empty pipeline (round-11 proven) ----
// CTA 128x128xBK64, 4 warps (2m x 2n), warp tile 64x64. 3 stages; 2 CTAs/SM.
// No __syncthreads in the mainloop: per-stage full (cp.async-armed, count=128) and
// empty (plain arrive, count=128) mbarriers; warps free-run within the stage ring.
#define BM 128
#define BN 128
#define BK 64
#define NSTAGE 3
#define A_BYTES (BM * BK * 2)                   // 16384
#define STAGE_BYTES ((BM + BN) * BK * 2)        // 32768
#define MBAR_OFF (NSTAGE * STAGE_BYTES)         // 98304
#define SMEM_BYTES (MBAR_OFF + 64)
#define NTHREADS 128

template <int KCHUNKS, bool FUSE_Q, typename OutT>
__global__ void __launch_bounds__(NTHREADS, 2)
h16_gemm(const __half* __restrict__ A, const __half* __restrict__ Bt,
         const float* __restrict__ bias,
         const float* __restrict__ theta, const float* __restrict__ wim,
         const float* __restrict__ qp,
         OutT* __restrict__ C, int Kdim, int Ndim)
{
    extern __shared__ char smem[];
    const uint32_t sb = smem_u32(smem);
    const int tid = threadIdx.x;
    const int wid = tid >> 5, lid = tid & 31;
    const int wm = wid & 1, wn = wid >> 1;            // warp grid 2(m) x 2(n)

    const uint32_t FULL  = sb + MBAR_OFF;              // full[s]  at +8*s
    const uint32_t EMPTY = sb + MBAR_OFF + 24;         // empty[s] at +8*s

    if (tid == 0) {
#pragma unroll
        for (int s = 0; s < NSTAGE; s++) {
            MBAR_INIT(FULL  + 8 * s, NTHREADS);
            MBAR_INIT(EMPTY + 8 * s, NTHREADS);
        }
    }
    __syncthreads();                                   // only CTA-wide sync (init visibility)

    const int tile_n = blockIdx.x, tile_m = blockIdx.y;
    const __half* Ab = A  + (size_t)tile_m * BM * Kdim;
    const __half* Bb = Bt + (size_t)tile_n * BN * Kdim;

    float acc[4][8][4];                                // 128 regs
#pragma unroll
    for (int i = 0; i < 4; i++)
#pragma unroll
        for (int j = 0; j < 8; j++)
#pragma unroll
            for (int q = 0; q < 4; q++) acc[i][j][q] = 0.0f;

    // ---- per-thread stage loader (16 x cp.async16), then arm the stage's full barrier ----
    auto load_chunk = [&](int c, int s) {
        const uint32_t a_s = sb + s * STAGE_BYTES;
        const uint32_t b_s = a_s + A_BYTES;
        const __half* ag = Ab + c * BK;
        const __half* bg = Bb + c * BK;
#pragma unroll
        for (int i = 0; i < 8; i++) {                  // A: 128 rows x 8 chunks
            int f = tid + i * NTHREADS;
            int r = f >> 3, kc = f & 7;
            uint32_t bo = (uint32_t)(r * 128 + kc * 16);
            cp_async16(a_s + sw128(bo), ag + (size_t)r * Kdim + kc * 8);
        }
#pragma unroll
        for (int i = 0; i < 8; i++) {                  // B: 128 rows x 8 chunks
            int f = tid + i * NTHREADS;
            int r = f >> 3, kc = f & 7;
            uint32_t bo = (uint32_t)(r * 128 + kc * 16);
            cp_async16(b_s + sw128(bo), bg + (size_t)r * Kdim + kc * 8);
        }
        CPASYNC_MBAR_ARRIVE(FULL + 8 * s);             // fires when this thread's loads land
    };

    // prologue: fill all 3 stages (chunks 0..2)
#pragma unroll
    for (int c = 0; c < NSTAGE && c < KCHUNKS; c++)
        load_chunk(c, c);

    // hoisted swizzled ldmatrix base offsets; ks*32 is XOR-composable (bits 5-6)
    const int a_row_base = wm * 64 + ((lid >> 3) & 1) * 8 + (lid & 7);
    const int a_byte     = ((lid >> 4) & 1) * 16;
    const int b_row_base = wn * 64 + ((lid >> 4) & 1) * 8 + (lid & 7);
    const int b_byte     = ((lid >> 3) & 1) * 16;
    const uint32_t a_off0 = sw128((uint32_t)(a_row_base * 128 + a_byte));
    const uint32_t b_off0 = sw128((uint32_t)(b_row_base * 128 + b_byte)) + A_BYTES;

    // cursors: consumer (cs,cp) over full[]; load-target (es,ep) over empty[]
    int cs = 0, cp = 0;
    int es = 0, ep = 0;

    for (int c = 0; c < KCHUNKS; c++) {
        // issue load for chunk c+NSTAGE-1 into the stage chunk c-1 just vacated
        if (c >= 1 && c + NSTAGE - 1 < KCHUNKS) {
            MBAR_WAIT(EMPTY + 8 * es, ep);             // all 128 threads done chunk c-1
            load_chunk(c + NSTAGE - 1, es);
            if (++es == NSTAGE) { es = 0; ep ^= 1; }
        }

        MBAR_WAIT(FULL + 8 * cs, cp);                  // chunk c resident

        const uint32_t st = sb + cs * STAGE_BYTES;
        const uint32_t a0 = st + a_off0;
        const uint32_t b0 = st + b_off0;
#pragma unroll
        for (int ks = 0; ks < 4; ks++) {               // 4 x k16 = BK 64
            const uint32_t kx = (uint32_t)(ks * 32);
            uint32_t af[4][4];
#pragma unroll
            for (int mt = 0; mt < 4; mt++)
                ldsm_x4(af[mt][0], af[mt][1], af[mt][2], af[mt][3],
                        (a0 + mt * 2048) ^ kx);
            uint32_t bf[8][2];
#pragma unroll
            for (int np = 0; np < 4; np++) {
                uint32_t r0, r1, r2, r3;
                ldsm_x4(r0, r1, r2, r3, (b0 + np * 2048) ^ kx);
                bf[np * 2 + 0][0] = r0; bf[np * 2 + 0][1] = r1;
                bf[np * 2 + 1][0] = r2; bf[np * 2 + 1][1] = r3;
            }
#pragma unroll
            for (int mt = 0; mt < 4; mt++)
#pragma unroll
                for (int nt = 0; nt < 8; nt++)
                    mma_f16(acc[mt][nt], af[mt], bf[nt]);
        }

        MBAR_ARRIVE(EMPTY + 8 * cs);                   // this thread done reading stage cs
        if (++cs == NSTAGE) { cs = 0; cp ^= 1; }
    }

    // ---- epilogue (acc in regs; no further smem hazards) ----
#pragma unroll
    for (int nt = 0; nt < 8; nt++) {
        const int n = tile_n * BN + wn * 64 + nt * 8 + (lid & 3) * 2;
        const float2 bb = *(const float2*)(bias + n);
        float2 th2 = {0.f, 0.f}, wi2 = {0.f, 0.f}, qp2 = {0.f, 0.f};
        if (FUSE_Q) {
            th2 = *(const float2*)(theta + n);
            wi2 = *(const float2*)(wim + n);
            qp2 = *(const float2*)(qp + n);
        }
#pragma unroll
        for (int mt = 0; mt < 4; mt++) {
#pragma unroll
            for (int h = 0; h < 2; h++) {
                const size_t row = (size_t)tile_m * BM + wm * 64 + mt * 16 + (lid >> 2) + h * 8;
                float v0 = acc[mt][nt][2 * h + 0] + bb.x;
                float v1 = acc[mt][nt][2 * h + 1] + bb.y;
                if (FUSE_Q) {
                    float im0 = wi2.x * __sinf(th2.x + v0 * 0.1f);
                    float im1 = wi2.y * __sinf(th2.y + v1 * 0.1f);
                    v0 = fmaf(qp2.x, im0, v0);
                    v1 = fmaf(qp2.y, im1, v1);
                    v0 = fmaxf(v0, 0.0f);
                    v1 = fmaxf(v1, 0.0f);
                }
                if (FUSE_Q) {
                    __half2 hv = __floats2half2_rn(v0, v1);
                    *(__half2*)((__half*)C + row * Ndim + n) = hv;
                } else {
                    *(float2*)((float*)C + row * Ndim + n) = make_float2(v0, v1);
                }
            }
        }
    }
}

// ---------------- host entry ----------------
extern "C" void kernel_launch(void* const* d_in, const int* in_sizes, int n_in,
                              void* d_out, int out_size)
{
    const float* x   = (const float*)d_in[0];
    const float* W1  = (const float*)d_in[1];
    const float* b1  = (const float*)d_in[2];
    const float* th  = (const float*)d_in[3];
    const float* wre = (const float*)d_in[4];
    const float* wim = (const float*)d_in[5];
    const float* W2  = (const float*)d_in[6];
    const float* b2  = (const float*)d_in[7];
    float* out = (float*)d_out;

    void *pxh, *pw1t, *pw2t, *pact, *pqp;
    cudaGetSymbolAddress(&pxh,  g_xh);
    cudaGetSymbolAddress(&pw1t, g_w1t);
    cudaGetSymbolAddress(&pw2t, g_w2t);
    cudaGetSymbolAddress(&pact, g_act);
    cudaGetSymbolAddress(&pqp,  g_qp);
    __half* xh  = (__half*)pxh;
    __half* w1t = (__half*)pw1t;
    __half* w2t = (__half*)pw2t;
    __half* act = (__half*)pact;
    float*  qp  = (float*)pqp;

    cudaFuncSetAttribute((const void*)h16_gemm<DMODEL / BK, true, __half>,
                         cudaFuncAttributeMaxDynamicSharedMemorySize, SMEM_BYTES);
    cudaFuncSetAttribute((const void*)h16_gemm<DFF / BK, false, float>,
                         cudaFuncAttributeMaxDynamicSharedMemorySize, SMEM_BYTES);

    // ONE preprocessing launch: x->fp16, qp, W1^T, W2^T (all independent block ranges)
    prep_all_k<<<PREP_BLOCKS, 256>>>(x, xh, th, wre, wim, qp, W1, w1t, W2, w2t);

    // GEMM1: act = fp16(relu(qt(x @ W1 + b1)))   [8192, 4096], grid (32, 64)
    h16_gemm<DMODEL / BK, true, __half><<<dim3(DFF / BN, MTOK / BM), NTHREADS, SMEM_BYTES>>>(
        xh, w1t, b1, th, wim, qp, act, DMODEL, DFF);

    // GEMM2: out = act @ W2 + b2                  [8192, 1024], grid (8, 64)
    h16_gemm<DFF / BK, false, float><<<dim3(DMODEL / BN, MTOK / BM), NTHREADS, SMEM_BYTES>>>(
        act, w2t, b2, nullptr, nullptr, nullptr, out, DFF, DMODEL);
}

// round 14
// speedup vs baseline: 1.0581x; 1.0130x over previous
#include <cuda_runtime.h>
#include <cuda_fp16.h>
#include <cstdint>
#include <math.h>

#define MTOK   8192
#define DMODEL 1024
#define DFF    4096

// ---------------- scratch (device globals; no runtime allocation) ----------------
__device__ __half g_xh [(size_t)MTOK * DMODEL];   // x in fp16
__device__ __half g_w1t[(size_t)DFF  * DMODEL];   // W1^T fp16  [N=4096][K=1024]
__device__ __half g_w2t[(size_t)DMODEL * DFF];    // W2^T fp16  [N=1024][K=4096]
__device__ __half g_act[(size_t)MTOK * DFF];      // post-activation hidden, fp16
__device__ float  g_qp [DFF];                     // (cos(th)*wre + sin(th)*wim)*0.1

// ---------------- helpers ----------------
__device__ __forceinline__ uint32_t smem_u32(const void* p) {
    uint32_t a;
    asm("{ .reg .u64 t; cvta.to.shared.u64 t, %1; cvt.u32.u64 %0, t; }" : "=r"(a) : "l"(p));
    return a;
}
__device__ __forceinline__ void cp_async16(uint32_t saddr, const void* g) {
    asm volatile("cp.async.cg.shared.global [%0], [%1], 16;" :: "r"(saddr), "l"(g) : "memory");
}
__device__ __forceinline__ void ldsm_x4(uint32_t& r0, uint32_t& r1, uint32_t& r2, uint32_t& r3,
                                        uint32_t addr) {
    asm volatile("ldmatrix.sync.aligned.m8n8.x4.shared.b16 {%0,%1,%2,%3}, [%4];"
                 : "=r"(r0), "=r"(r1), "=r"(r2), "=r"(r3) : "r"(addr));
}
__device__ __forceinline__ void mma_f16(float* c, const uint32_t* a, const uint32_t* b) {
    asm volatile(
        "mma.sync.aligned.m16n8k16.row.col.f32.f16.f16.f32 "
        "{%0,%1,%2,%3}, {%4,%5,%6,%7}, {%8,%9}, {%0,%1,%2,%3};"
        : "+f"(c[0]), "+f"(c[1]), "+f"(c[2]), "+f"(c[3])
        : "r"(a[0]), "r"(a[1]), "r"(a[2]), "r"(a[3]), "r"(b[0]), "r"(b[1]));
}
__device__ __forceinline__ uint32_t sw128(uint32_t bo) { return bo ^ ((bo >> 3) & 0x70); }

// mbarrier primitives (baseline sm_100-legal)
#define MBAR_INIT(a, n)  asm volatile("mbarrier.init.shared.b64 [%0], %1;" :: "r"(a), "r"(n) : "memory")
#define MBAR_ARRIVE(a)   asm volatile("mbarrier.arrive.shared.b64 _, [%0];" :: "r"(a) : "memory")
#define CPASYNC_MBAR_ARRIVE(a) \
    asm volatile("cp.async.mbarrier.arrive.noinc.shared.b64 [%0];" :: "r"(a) : "memory")
#define MBAR_WAIT(a, ph) do {                                                             \
    uint32_t _m = (a), _p = (ph), _d;                                                     \
    asm volatile("{ .reg .pred p; mbarrier.try_wait.parity.acquire.cta.shared::cta.b64 p, [%1], %2; selp.b32 %0,1,0,p; }" \
        : "=r"(_d) : "r"(_m), "r"(_p) : "memory");                                        \
    if (!_d) {                                                                            \
        asm volatile("{ .reg .pred P1; WL_%=: mbarrier.try_wait.parity.acquire.cta.shared::cta.b64 P1, [%0], %1, 0x989680; @P1 bra.uni WD_%=; bra.uni WL_%=; WD_%=: }" \
            :: "r"(_m), "r"(_p) : "memory");                                              \
    } } while (0)

// ---------------- single fused preprocessing kernel (bandwidth-tuned) ----------------
// Blocks [0, XB):       x fp32 -> fp16, 8 elems/thread (2x float4 read, 1x uint4 write)
// Blocks [XB, +QB):     qp = (cos(th)*wre + sin(th)*wim)*0.1
// Blocks [+QB, +W1T):   W1 (1024x4096) -> w1t transpose, 64row x 32col tiles
// Blocks [+W1T, +W2T):  W2 (4096x1024) -> w2t transpose
#define PREP_XB  (MTOK * DMODEL / 8 / 256)              // 4096
#define PREP_QB  (DFF / 256)                            // 16
#define W1_TILES ((DFF / 32) * (DMODEL / 64))           // 128 * 16 = 2048
#define W2_TILES ((DMODEL / 32) * (DFF / 64))           // 32 * 64  = 2048
#define PREP_BLOCKS (PREP_XB + PREP_QB + W1_TILES + W2_TILES)

__global__ void prep_all_k(const float* __restrict__ x, __half* __restrict__ xh,
                           const float* __restrict__ th, const float* __restrict__ wre,
                           const float* __restrict__ wim, float* __restrict__ qp,
                           const float* __restrict__ W1, __half* __restrict__ w1t,
                           const float* __restrict__ W2, __half* __restrict__ w2t) {
    __shared__ float t[32][65];    // [col][row], pad 65: store stride 65 % 32 == 1 -> conflict-free
    int b = blockIdx.x;
    if (b < PREP_XB) {
        int i = (b * 256 + threadIdx.x) * 2;           // index of first float4
        float4 v0 = ((const float4*)x)[i];
        float4 v1 = ((const float4*)x)[i + 1];
        __half2 h0 = __floats2half2_rn(v0.x, v0.y);
        __half2 h1 = __floats2half2_rn(v0.z, v0.w);
        __half2 h2 = __floats2half2_rn(v1.x, v1.y);
        __half2 h3 = __floats2half2_rn(v1.z, v1.w);
        uint4 o;
        o.x = *(uint32_t*)&h0; o.y = *(uint32_t*)&h1;
        o.z = *(uint32_t*)&h2; o.w = *(uint32_t*)&h3;
        ((uint4*)xh)[i >> 1] = o;
        return;
    }
    b -= PREP_XB;
    if (b < PREP_QB) {
        int i = b * 256 + threadIdx.x;
        float s, c; sincosf(th[i], &s, &c);
        qp[i] = (c * wre[i] + s * wim[i]) * 0.1f;
        return;
    }
    b -= PREP_QB;
    // transpose: in[R][C] -> out[C][R], tile = 64 rows x 32 cols of in
    const float* in; __half* out; int R, C, tile;
    if (b < W1_TILES) { in = W1; out = w1t; R = DMODEL; C = DFF;    tile = b; }
    else              { in = W2; out = w2t; R = DFF;    C = DMODEL; tile = b - W1_TILES; }
    const int tiles_x = C / 32;
    const int bx = (tile % tiles_x) * 32;              // col offset in C
    const int by = (tile / tiles_x) * 64;              // row offset in R
    const int lid = threadIdx.x & 31, grp = threadIdx.x >> 5;   // 8 groups
    // load: 64 rows x 32 cols; thread (grp,lid) loads rows grp+8i, col lid (128B coalesced)
#pragma unroll
    for (int i = 0; i < 8; i++) {
        int r = grp + 8 * i;
        t[lid][r] = in[(size_t)(by + r) * C + bx + lid];
    }
    __syncthreads();
    // write: out rows bx+c (32 of them), each 64 consecutive halfs (128B coalesced, half2)
#pragma unroll
    for (int i = 0; i < 4; i++) {
        int c = grp + 8 * i;
        __half2 hv = __floats2half2_rn(t[c][2 * lid], t[c][2 * lid + 1]);
        *(__half2*)(out + (size_t)(bx + c) * R + by + 2 * lid) = hv;
    }
}

// ---------------- fp16 mma.sync GEMM, mbarrier full/empty pipeline (round-11 proven) ----
// CTA 128x128xBK64, 4 warps (2m x 2n), warp tile 64x64. 3 stages; 2 CTAs/SM.
#define BM 128
#define BN 128
#define BK 64
#define NSTAGE 3
#define A_BYTES (BM * BK * 2)                   // 16384
#define STAGE_BYTES ((BM + BN) * BK * 2)        // 32768
#define MBAR_OFF (NSTAGE * STAGE_BYTES)         // 98304
#define SMEM_BYTES (MBAR_OFF + 64)
#define NTHREADS 128

template <int KCHUNKS, bool FUSE_Q, typename OutT>
__global__ void __launch_bounds__(NTHREADS, 2)
h16_gemm(const __half* __restrict__ A, const __half* __restrict__ Bt,
         const float* __restrict__ bias,
         const float* __restrict__ theta, const float* __restrict__ wim,
         const float* __restrict__ qp,
         OutT* __restrict__ C, int Kdim, int Ndim)
{
    extern __shared__ char smem[];
    const uint32_t sb = smem_u32(smem);
    const int tid = threadIdx.x;
    const int wid = tid >> 5, lid = tid & 31;
    const int wm = wid & 1, wn = wid >> 1;            // warp grid 2(m) x 2(n)

    const uint32_t FULL  = sb + MBAR_OFF;              // full[s]  at +8*s
    const uint32_t EMPTY = sb + MBAR_OFF + 24;         // empty[s] at +8*s

    if (tid == 0) {
#pragma unroll
        for (int s = 0; s < NSTAGE; s++) {
            MBAR_INIT(FULL  + 8 * s, NTHREADS);
            MBAR_INIT(EMPTY + 8 * s, NTHREADS);
        }
    }
    __syncthreads();                                   // only CTA-wide sync (init visibility)

    const int tile_n = blockIdx.x, tile_m = blockIdx.y;
    const __half* Ab = A  + (size_t)tile_m * BM * Kdim;
    const __half* Bb = Bt + (size_t)tile_n * BN * Kdim;

    float acc[4][8][4];                                // 128 regs
#pragma unroll
    for (int i = 0; i < 4; i++)
#pragma unroll
        for (int j = 0; j < 8; j++)
#pragma unroll
            for (int q = 0; q < 4; q++) acc[i][j][q] = 0.0f;

    // ---- per-thread stage loader (16 x cp.async16), then arm the stage's full barrier ----
    auto load_chunk = [&](int c, int s) {
        const uint32_t a_s = sb + s * STAGE_BYTES;
        const uint32_t b_s = a_s + A_BYTES;
        const __half* ag = Ab + c * BK;
        const __half* bg = Bb + c * BK;
#pragma unroll
        for (int i = 0; i < 8; i++) {                  // A: 128 rows x 8 chunks
            int f = tid + i * NTHREADS;
            int r = f >> 3, kc = f & 7;
            uint32_t bo = (uint32_t)(r * 128 + kc * 16);
            cp_async16(a_s + sw128(bo), ag + (size_t)r * Kdim + kc * 8);
        }
#pragma unroll
        for (int i = 0; i < 8; i++) {                  // B: 128 rows x 8 chunks
            int f = tid + i * NTHREADS;
            int r = f >> 3, kc = f & 7;
            uint32_t bo = (uint32_t)(r * 128 + kc * 16);
            cp_async16(b_s + sw128(bo), bg + (size_t)r * Kdim + kc * 8);
        }
        CPASYNC_MBAR_ARRIVE(FULL + 8 * s);             // fires when this thread's loads land
    };

    // prologue: fill all 3 stages (chunks 0..2)
#pragma unroll
    for (int c = 0; c < NSTAGE && c < KCHUNKS; c++)
        load_chunk(c, c);

    // hoisted swizzled ldmatrix base offsets; ks*32 is XOR-composable (bits 5-6)
    const int a_row_base = wm * 64 + ((lid >> 3) & 1) * 8 + (lid & 7);
    const int a_byte     = ((lid >> 4) & 1) * 16;
    const int b_row_base = wn * 64 + ((lid >> 4) & 1) * 8 + (lid & 7);
    const int b_byte     = ((lid >> 3) & 1) * 16;
    const uint32_t a_off0 = sw128((uint32_t)(a_row_base * 128 + a_byte));
    const uint32_t b_off0 = sw128((uint32_t)(b_row_base * 128 + b_byte)) + A_BYTES;

    // cursors: consumer (cs,cp) over full[]; load-target (es,ep) over empty[]
    int cs = 0, cp = 0;
    int es = 0, ep = 0;

    for (int c = 0; c < KCHUNKS; c++) {
        // issue load for chunk c+NSTAGE-1 into the stage chunk c-1 just vacated
        if (c >= 1 && c + NSTAGE - 1 < KCHUNKS) {
            MBAR_WAIT(EMPTY + 8 * es, ep);             // all 128 threads done chunk c-1
            load_chunk(c + NSTAGE - 1, es);
            if (++es == NSTAGE) { es = 0; ep ^= 1; }
        }

        MBAR_WAIT(FULL + 8 * cs, cp);                  // chunk c resident

        const uint32_t st = sb + cs * STAGE_BYTES;
        const uint32_t a0 = st + a_off0;
        const uint32_t b0 = st + b_off0;
#pragma unroll
        for (int ks = 0; ks < 4; ks++) {               // 4 x k16 = BK 64
            const uint32_t kx = (uint32_t)(ks * 32);
            uint32_t af[4][4];
#pragma unroll
            for (int mt = 0; mt < 4; mt++)
                ldsm_x4(af[mt][0], af[mt][1], af[mt][2], af[mt][3],
                        (a0 + mt * 2048) ^ kx);
            uint32_t bf[8][2];
#pragma unroll
            for (int np = 0; np < 4; np++) {
                uint32_t r0, r1, r2, r3;
                ldsm_x4(r0, r1, r2, r3, (b0 + np * 2048) ^ kx);
                bf[np * 2 + 0][0] = r0; bf[np * 2 + 0][1] = r1;
                bf[np * 2 + 1][0] = r2; bf[np * 2 + 1][1] = r3;
            }
#pragma unroll
            for (int mt = 0; mt < 4; mt++)
#pragma unroll
                for (int nt = 0; nt < 8; nt++)
                    mma_f16(acc[mt][nt], af[mt], bf[nt]);
        }

        MBAR_ARRIVE(EMPTY + 8 * cs);                   // this thread done reading stage cs
        if (++cs == NSTAGE) { cs = 0; cp ^= 1; }
    }

    // ---- epilogue (acc in regs; no further smem hazards) ----
#pragma unroll
    for (int nt = 0; nt < 8; nt++) {
        const int n = tile_n * BN + wn * 64 + nt * 8 + (lid & 3) * 2;
        const float2 bb = *(const float2*)(bias + n);
        float2 th2 = {0.f, 0.f}, wi2 = {0.f, 0.f}, qp2 = {0.f, 0.f};
        if (FUSE_Q) {
            th2 = *(const float2*)(theta + n);
            wi2 = *(const float2*)(wim + n);
            qp2 = *(const float2*)(qp + n);
        }
#pragma unroll
        for (int mt = 0; mt < 4; mt++) {
#pragma unroll
            for (int h = 0; h < 2; h++) {
                const size_t row = (size_t)tile_m * BM + wm * 64 + mt * 16 + (lid >> 2) + h * 8;
                float v0 = acc[mt][nt][2 * h + 0] + bb.x;
                float v1 = acc[mt][nt][2 * h + 1] + bb.y;
                if (FUSE_Q) {
                    float im0 = wi2.x * __sinf(th2.x + v0 * 0.1f);
                    float im1 = wi2.y * __sinf(th2.y + v1 * 0.1f);
                    v0 = fmaf(qp2.x, im0, v0);
                    v1 = fmaf(qp2.y, im1, v1);
                    v0 = fmaxf(v0, 0.0f);
                    v1 = fmaxf(v1, 0.0f);
                }
                if (FUSE_Q) {
                    __half2 hv = __floats2half2_rn(v0, v1);
                    *(__half2*)((__half*)C + row * Ndim + n) = hv;
                } else {
                    *(float2*)((float*)C + row * Ndim + n) = make_float2(v0, v1);
                }
            }
        }
    }
}

// ---------------- host entry ----------------
extern "C" void kernel_launch(void* const* d_in, const int* in_sizes, int n_in,
                              void* d_out, int out_size)
{
    const float* x   = (const float*)d_in[0];
    const float* W1  = (const float*)d_in[1];
    const float* b1  = (const float*)d_in[2];
    const float* th  = (const float*)d_in[3];
    const float* wre = (const float*)d_in[4];
    const float* wim = (const float*)d_in[5];
    const float* W2  = (const float*)d_in[6];
    const float* b2  = (const float*)d_in[7];
    float* out = (float*)d_out;

    void *pxh, *pw1t, *pw2t, *pact, *pqp;
    cudaGetSymbolAddress(&pxh,  g_xh);
    cudaGetSymbolAddress(&pw1t, g_w1t);
    cudaGetSymbolAddress(&pw2t, g_w2t);
    cudaGetSymbolAddress(&pact, g_act);
    cudaGetSymbolAddress(&pqp,  g_qp);
    __half* xh  = (__half*)pxh;
    __half* w1t = (__half*)pw1t;
    __half* w2t = (__half*)pw2t;
    __half* act = (__half*)pact;
    float*  qp  = (float*)pqp;

    cudaFuncSetAttribute((const void*)h16_gemm<DMODEL / BK, true, __half>,
                         cudaFuncAttributeMaxDynamicSharedMemorySize, SMEM_BYTES);
    cudaFuncSetAttribute((const void*)h16_gemm<DFF / BK, false, float>,
                         cudaFuncAttributeMaxDynamicSharedMemorySize, SMEM_BYTES);

    // ONE preprocessing launch: x->fp16, qp, W1^T, W2^T (independent block ranges)
    prep_all_k<<<PREP_BLOCKS, 256>>>(x, xh, th, wre, wim, qp, W1, w1t, W2, w2t);

    // GEMM1: act = fp16(relu(qt(x @ W1 + b1)))   [8192, 4096], grid (32, 64)
    h16_gemm<DMODEL / BK, true, __half><<<dim3(DFF / BN, MTOK / BM), NTHREADS, SMEM_BYTES>>>(
        xh, w1t, b1, th, wim, qp, act, DMODEL, DFF);

    // GEMM2: out = act @ W2 + b2                  [8192, 1024], grid (8, 64)
    h16_gemm<DFF / BK, false, float><<<dim3(DMODEL / BN, MTOK / BM), NTHREADS, SMEM_BYTES>>>(
        act, w2t, b2, nullptr, nullptr, nullptr, out, DFF, DMODEL);
}